// round 2
// baseline (speedup 1.0000x reference)
#include <cuda_runtime.h>
#include <math.h>

#define Nn 80000
#define Uu 40000
#define Dd 128
#define Ee 1600000
#define Lh 17   // K+1 keys

// ---------------- scratch (static device globals: no allocation) ----------------
__device__ float g_tmp[Nn * Dd];
__device__ float g_Q[Nn * Dd];
__device__ float g_KT[2 * Nn * Dd];   // K projected with set-s weights, all N nodes
__device__ float g_VT[2 * Nn * Dd];   // V projected with set-s weights, all N nodes
__device__ float g_O[Nn * Dd];
__device__ float g_e[Nn * Dd];
__device__ float g_total[Nn * Dd];
__device__ float g_posK[2 * Lh * Dd];
__device__ float g_posV[2 * Lh * Dd];
__device__ float g_posQ0[2 * Dd];
__device__ int   g_cnt[Nn];
__device__ int   g_rowptr[Nn + 1];
__device__ int   g_scol[Ee];
__device__ float g_sval[Ee];

// ---------------- init: e = concat(user,item); total = e ----------------
__global__ void k_init(const float* __restrict__ ue, const float* __restrict__ ie) {
    int i = blockIdx.x * blockDim.x + threadIdx.x;
    if (i >= Nn * Dd) return;
    float v = (i < Uu * Dd) ? ue[i] : ie[i - Uu * Dd];
    g_e[i] = v;
    g_total[i] = v;
}

// ---------------- CSR build ----------------
__global__ void k_hist(const int* __restrict__ rows) {
    int i = blockIdx.x * blockDim.x + threadIdx.x;
    if (i < Ee) atomicAdd(&g_cnt[rows[i]], 1);
}

// single-block exclusive scan of g_cnt -> g_rowptr
__global__ void k_scan() {
    __shared__ int ssum[1024];
    const int t = threadIdx.x;
    const int CH = (Nn + 1023) / 1024;  // 79
    int lo = t * CH;
    int hi = lo + CH; if (hi > Nn) hi = Nn;
    if (lo > Nn) lo = Nn;
    int s = 0;
    for (int r = lo; r < hi; r++) s += g_cnt[r];
    ssum[t] = s;
    __syncthreads();
    for (int off = 1; off < 1024; off <<= 1) {
        int v = (t >= off) ? ssum[t - off] : 0;
        __syncthreads();
        ssum[t] += v;
        __syncthreads();
    }
    int base = (t == 0) ? 0 : ssum[t - 1];
    for (int r = lo; r < hi; r++) { g_rowptr[r] = base; base += g_cnt[r]; }
    if (t == 1023) g_rowptr[Nn] = ssum[1023];
}

__global__ void k_scatter(const int* __restrict__ rows, const int* __restrict__ cols,
                          const float* __restrict__ vals) {
    int i = blockIdx.x * blockDim.x + threadIdx.x;
    if (i >= Ee) return;
    int r = rows[i];
    int p = g_rowptr[r] + atomicAdd(&g_cnt[r], 1);
    g_scol[p] = cols[i];
    g_sval[p] = vals[i];
}

// ---------------- SpMM (CSR, one warp per row) ----------------
__global__ void __launch_bounds__(256) k_spmm() {
    int w = (blockIdx.x * 256 + threadIdx.x) >> 5;
    if (w >= Nn) return;
    int lane = threadIdx.x & 31;
    int j0 = g_rowptr[w], j1 = g_rowptr[w + 1];
    float4 acc = make_float4(0.f, 0.f, 0.f, 0.f);
    for (int j = j0; j < j1; j++) {
        int   c = g_scol[j];
        float v = g_sval[j];
        float4 ev = *(const float4*)&g_e[c * Dd + lane * 4];
        acc.x += v * ev.x; acc.y += v * ev.y; acc.z += v * ev.z; acc.w += v * ev.w;
    }
    *(float4*)&g_tmp[w * Dd + lane * 4] = acc;
}

// ---------------- projected positional embeddings (biases are zero-extended via GEMM path) ----
// 70 blocks of 128 threads: per (set in {u,i}) x (Q0, K l=0..16, V l=0..16)
__global__ void k_pos(const float* __restrict__ pos, const float* __restrict__ u_in_w,
                      const float* __restrict__ i_in_w) {
    int bid = blockIdx.x;
    int set = bid / 35;
    int r = bid % 35;
    const float* w = set ? i_in_w : u_in_w;
    const float* prow;
    float* out;
    if (r == 0)      { prow = pos;                 w += 0;           out = &g_posQ0[set * Dd]; }
    else if (r < 18) { int l = r - 1;  prow = pos + l * Dd; w += Dd * Dd;     out = &g_posK[(set * Lh + l) * Dd]; }
    else             { int l = r - 18; prow = pos + l * Dd; w += 2 * Dd * Dd; out = &g_posV[(set * Lh + l) * Dd]; }
    __shared__ float p[Dd];
    p[threadIdx.x] = prow[threadIdx.x];
    __syncthreads();
    int j = threadIdx.x;
    float acc = 0.f;
    #pragma unroll 4
    for (int k = 0; k < Dd; k++) acc += p[k] * w[j * 128 + k];
    out[j] = acc;
}

// ---------------- GEMM: out[r,:] = in[r,:] @ w^T + bias  (w is [128,128] row-major) ----------------
// optional: += resid, and total += result
__global__ void __launch_bounds__(256) k_gemm(const float* __restrict__ in,
                                              const float* __restrict__ w,
                                              const float* __restrict__ bias,
                                              float* __restrict__ out,
                                              int rowStart,
                                              const float* __restrict__ resid,
                                              float* __restrict__ total) {
    __shared__ float ws[16 * 132];  // transposed chunk: ws[kk*132 + j] = w[j*128 + kc+kk]
    __shared__ float xs[64 * 16];   // xs[r*16 + kk]
    const int t = threadIdx.x;
    const int row0 = rowStart + blockIdx.x * 64;
    const int colBase = (t & 31) * 4;
    const int rowBase = (t >> 5) * 8;
    const int xr = t >> 2;
    const int xk = (t & 3) * 4;

    float acc[8][4];
    #pragma unroll
    for (int r = 0; r < 8; r++) { acc[r][0] = 0.f; acc[r][1] = 0.f; acc[r][2] = 0.f; acc[r][3] = 0.f; }

    for (int kc = 0; kc < 128; kc += 16) {
        #pragma unroll
        for (int i = 0; i < 8; i++) {
            int idx = t + i * 256;
            int j = idx >> 4, kk = idx & 15;
            ws[kk * 132 + j] = w[j * 128 + kc + kk];
        }
        float4 xv4 = *(const float4*)&in[(row0 + xr) * 128 + kc + xk];
        *(float4*)&xs[xr * 16 + xk] = xv4;
        __syncthreads();
        #pragma unroll
        for (int kk = 0; kk < 16; kk += 4) {
            float4 w0 = *(const float4*)&ws[(kk + 0) * 132 + colBase];
            float4 w1 = *(const float4*)&ws[(kk + 1) * 132 + colBase];
            float4 w2 = *(const float4*)&ws[(kk + 2) * 132 + colBase];
            float4 w3 = *(const float4*)&ws[(kk + 3) * 132 + colBase];
            #pragma unroll
            for (int rr = 0; rr < 8; rr++) {
                float4 xv = *(const float4*)&xs[(rowBase + rr) * 16 + kk];
                acc[rr][0] += xv.x * w0.x; acc[rr][0] += xv.y * w1.x; acc[rr][0] += xv.z * w2.x; acc[rr][0] += xv.w * w3.x;
                acc[rr][1] += xv.x * w0.y; acc[rr][1] += xv.y * w1.y; acc[rr][1] += xv.z * w2.y; acc[rr][1] += xv.w * w3.y;
                acc[rr][2] += xv.x * w0.z; acc[rr][2] += xv.y * w1.z; acc[rr][2] += xv.z * w2.z; acc[rr][2] += xv.w * w3.z;
                acc[rr][3] += xv.x * w0.w; acc[rr][3] += xv.y * w1.w; acc[rr][3] += xv.z * w2.w; acc[rr][3] += xv.w * w3.w;
            }
        }
        __syncthreads();
    }

    float4 bv = *(const float4*)&bias[colBase];
    #pragma unroll
    for (int rr = 0; rr < 8; rr++) {
        int r = row0 + rowBase + rr;
        int ofs = r * 128 + colBase;
        float4 o;
        o.x = acc[rr][0] + bv.x; o.y = acc[rr][1] + bv.y;
        o.z = acc[rr][2] + bv.z; o.w = acc[rr][3] + bv.w;
        if (resid) {
            float4 rv = *(const float4*)&resid[ofs];
            o.x += rv.x; o.y += rv.y; o.z += rv.z; o.w += rv.w;
        }
        *(float4*)&out[ofs] = o;
        if (total) {
            float4 tv = *(const float4*)&total[ofs];
            tv.x += o.x; tv.y += o.y; tv.z += o.z; tv.w += o.w;
            *(float4*)&total[ofs] = tv;
        }
    }
}

// ---------------- attention: one warp per node ----------------
// lane*4 covers head h=lane>>3, dims (lane&7)*4 .. +3  (head-major layout matches reshape(H,dh))
// K/V gathered from the QUERY-SET's projection table (samples cross sets; weights follow the query).
__global__ void __launch_bounds__(256) k_attn(const int* __restrict__ samples) {
    int w = (blockIdx.x * 256 + threadIdx.x) >> 5;
    if (w >= Nn) return;
    int lane = threadIdx.x & 31;
    int set = (w < Uu) ? 0 : 1;
    const float* Kt = &g_KT[set * (Nn * Dd)];
    const float* Vt = &g_VT[set * (Nn * Dd)];
    const float* pk = &g_posK[set * Lh * Dd];
    const float* pv = &g_posV[set * Lh * Dd];
    const float* pq = &g_posQ0[set * Dd];
    int c4 = lane * 4;

    float4 qv = *(const float4*)&g_Q[w * Dd + c4];
    float4 pqv = *(const float4*)&pq[c4];
    float qx = qv.x + pqv.x, qy = qv.y + pqv.y, qz = qv.z + pqv.z, qw = qv.w + pqv.w;

    int sidx[Lh];
    sidx[0] = w;
    #pragma unroll
    for (int l = 1; l < Lh; l++) sidx[l] = samples[w * 16 + (l - 1)];

    const float scale = 0.17677669529663687f;  // 1/sqrt(32)
    float sc[Lh];
    #pragma unroll
    for (int l = 0; l < Lh; l++) {
        float4 kv = *(const float4*)&Kt[sidx[l] * Dd + c4];
        float4 pkv = *(const float4*)&pk[l * Dd + c4];
        float d = qx * (kv.x + pkv.x) + qy * (kv.y + pkv.y) + qz * (kv.z + pkv.z) + qw * (kv.w + pkv.w);
        d += __shfl_xor_sync(0xffffffffu, d, 1);
        d += __shfl_xor_sync(0xffffffffu, d, 2);
        d += __shfl_xor_sync(0xffffffffu, d, 4);
        sc[l] = d * scale;
    }
    float m = sc[0];
    #pragma unroll
    for (int l = 1; l < Lh; l++) m = fmaxf(m, sc[l]);
    float s = 0.f;
    #pragma unroll
    for (int l = 0; l < Lh; l++) { sc[l] = __expf(sc[l] - m); s += sc[l]; }
    float inv = 1.f / s;

    float ox = 0.f, oy = 0.f, oz = 0.f, ow = 0.f;
    #pragma unroll
    for (int l = 0; l < Lh; l++) {
        float wgt = sc[l] * inv;
        float4 vv = *(const float4*)&Vt[sidx[l] * Dd + c4];
        float4 pvv = *(const float4*)&pv[l * Dd + c4];
        ox += wgt * (vv.x + pvv.x); oy += wgt * (vv.y + pvv.y);
        oz += wgt * (vv.z + pvv.z); ow += wgt * (vv.w + pvv.w);
    }
    float4 o = make_float4(ox, oy, oz, ow);
    *(float4*)&g_O[w * Dd + c4] = o;
}

// ---------------- output: d_out = [total ; total[:U] ; total[U:]] = [total ; total] ----------------
__global__ void k_out(float* __restrict__ out) {
    int i = blockIdx.x * blockDim.x + threadIdx.x;
    if (i >= Nn * Dd) return;
    float v = g_total[i];
    out[i] = v;
    out[Nn * Dd + i] = v;
}

extern "C" void kernel_launch(void* const* d_in, const int* in_sizes, int n_in,
                              void* d_out, int out_size) {
    (void)in_sizes; (void)n_in; (void)out_size;
    const int*   adj_rows = (const int*)d_in[0];
    const int*   adj_cols = (const int*)d_in[1];
    const float* adj_vals = (const float*)d_in[2];
    const int*   samples  = (const int*)d_in[3];
    const float* user_emb = (const float*)d_in[4];
    const float* item_emb = (const float*)d_in[5];
    const float* pos_emb  = (const float*)d_in[6];
    const float* u_in_w   = (const float*)d_in[7];
    const float* u_in_b   = (const float*)d_in[8];
    const float* u_out_w  = (const float*)d_in[9];
    const float* u_out_b  = (const float*)d_in[10];
    const float* i_in_w   = (const float*)d_in[11];
    const float* i_in_b   = (const float*)d_in[12];
    const float* i_out_w  = (const float*)d_in[13];
    const float* i_out_b  = (const float*)d_in[14];
    float* out = (float*)d_out;

    void *cntP, *tmpP, *qP, *ktP, *vtP, *oP, *eP, *totP;
    cudaGetSymbolAddress(&cntP, g_cnt);
    cudaGetSymbolAddress(&tmpP, g_tmp);
    cudaGetSymbolAddress(&qP, g_Q);
    cudaGetSymbolAddress(&ktP, g_KT);
    cudaGetSymbolAddress(&vtP, g_VT);
    cudaGetSymbolAddress(&oP, g_O);
    cudaGetSymbolAddress(&eP, g_e);
    cudaGetSymbolAddress(&totP, g_total);
    float* gTmp = (float*)tmpP;
    float* gQ  = (float*)qP;
    float* gKT = (float*)ktP;
    float* gVT = (float*)vtP;
    float* gO  = (float*)oP;
    float* gE  = (float*)eP;
    float* gTot = (float*)totP;

    // CSR build (adjacency constant within a call; rebuilt every call for determinism)
    cudaMemsetAsync(cntP, 0, Nn * sizeof(int));
    k_hist<<<(Ee + 255) / 256, 256>>>(adj_rows);
    k_scan<<<1, 1024>>>();
    cudaMemsetAsync(cntP, 0, Nn * sizeof(int));
    k_scatter<<<(Ee + 255) / 256, 256>>>(adj_rows, adj_cols, adj_vals);

    k_init<<<(Nn * Dd) / 256, 256>>>(user_emb, item_emb);
    k_pos<<<70, 128>>>(pos_emb, u_in_w, i_in_w);

    const int HB = Uu / 64;   // 625  (half: one set's query rows)
    const int FB = Nn / 64;   // 1250 (full: all N rows)
    for (int blk = 0; blk < 2; blk++) {
        k_spmm<<<(Nn * 32) / 256, 256>>>();
        // Q: per-set over own rows only (queries never cross sets)
        k_gemm<<<HB, 256>>>(gTmp, u_in_w, u_in_b, gQ, 0,  nullptr, nullptr);
        k_gemm<<<HB, 256>>>(gTmp, i_in_w, i_in_b, gQ, Uu, nullptr, nullptr);
        // K,V: BOTH weight sets over ALL N rows (samples cross sets; projection follows the query set)
        k_gemm<<<FB, 256>>>(gTmp, u_in_w + Dd * Dd,     u_in_b + Dd,     gKT,            0, nullptr, nullptr);
        k_gemm<<<FB, 256>>>(gTmp, i_in_w + Dd * Dd,     i_in_b + Dd,     gKT + Nn * Dd,  0, nullptr, nullptr);
        k_gemm<<<FB, 256>>>(gTmp, u_in_w + 2 * Dd * Dd, u_in_b + 2 * Dd, gVT,            0, nullptr, nullptr);
        k_gemm<<<FB, 256>>>(gTmp, i_in_w + 2 * Dd * Dd, i_in_b + 2 * Dd, gVT + Nn * Dd,  0, nullptr, nullptr);
        k_attn<<<(Nn * 32) / 256, 256>>>(samples);
        // out-projection + residual(tmp) -> new e; total += e
        k_gemm<<<HB, 256>>>(gO, u_out_w, u_out_b, gE, 0,  gTmp, gTot);
        k_gemm<<<HB, 256>>>(gO, i_out_w, i_out_b, gE, Uu, gTmp, gTot);
    }
    k_out<<<(Nn * Dd) / 256, 256>>>(out);
}